// round 1
// baseline (speedup 1.0000x reference)
#include <cuda_runtime.h>
#include <cstdint>

// Problem constants (fixed-shape problem: H=8, MH=8, N_NODES=500000)
#define H_DIM 8
#define MH_DIM 8
#define FEAT 64              // H*MH per sign
#define REC 128              // 2 signs * FEAT floats per node record
#define MAX_NODES 500000

// Node-major scratch: [node][sign][h][mh], 512B per node, deg-normalization folded in.
__device__ float g_pk[(size_t)MAX_NODES * REC];

// ---------------------------------------------------------------------------
// Kernel 1: transpose [s][h][mh][N] (feature-major) -> [N][s][h][mh],
// multiplying by 1/max(deg,1) on the fly.
// Block: 256 threads handles a tile of 32 nodes x 128 features.
// ---------------------------------------------------------------------------
__global__ __launch_bounds__(256) void transpose_fold_kernel(
    const float* __restrict__ phi_pos,
    const float* __restrict__ phi_neg,
    const float* __restrict__ deg_pos,
    const float* __restrict__ deg_neg,
    int n_nodes)
{
    __shared__ float tile[REC][33];     // [feat][node], pad 33 to kill bank conflicts
    __shared__ float inv[2][32][H_DIM]; // 1/max(deg,1) per (sign, node, head)

    const int k0 = blockIdx.x * 32;
    const int t  = threadIdx.x;

    // Load deg tiles (contiguous: deg_* is [N][H]) and invert with clamp.
    #pragma unroll
    for (int it = 0; it < 2; ++it) {
        int idx  = t + it * 256;          // 0..511 : s*256 + node*8 + h
        int s    = idx >> 8;
        int node = (idx >> 3) & 31;
        int h    = idx & 7;
        int k    = k0 + node;
        float d  = 1.0f;
        if (k < n_nodes) {
            const float* dp = s ? deg_neg : deg_pos;
            d = dp[(size_t)k * H_DIM + h];
        }
        inv[s][node][h] = 1.0f / fmaxf(d, 1.0f);
    }

    // Coalesced loads along the node (k) axis: 128 feature-rows x 32 nodes.
    #pragma unroll
    for (int it = 0; it < 16; ++it) {
        int l  = t + it * 256;
        int r  = l >> 5;        // feature row 0..127
        int kk = l & 31;        // node within tile
        int k  = k0 + kk;
        int s  = r >> 6;
        int f  = r & 63;        // h*8+mh
        float v = 0.0f;
        if (k < n_nodes) {
            const float* src = s ? phi_neg : phi_pos;
            v = __ldg(src + (size_t)f * n_nodes + k);
        }
        tile[r][kk] = v;
    }
    __syncthreads();

    // Coalesced node-major writes (32 nodes * 512B = contiguous 16KB span).
    #pragma unroll
    for (int it = 0; it < 16; ++it) {
        int p    = t + it * 256;
        int node = p >> 7;
        int f    = p & 127;
        int k    = k0 + node;
        if (k < n_nodes) {
            int s = f >> 6;
            int h = (f >> 3) & 7;
            g_pk[(size_t)k * REC + f] = tile[f][node] * inv[s][node][h];
        }
    }
}

// ---------------------------------------------------------------------------
// Kernel 2: gather + dot. 8 threads per query; thread j handles head j for
// both signs. All loads are float4, gathers hit one 512B-contiguous record.
// out layout: [pos: nq*8][neg: nq*8]
// ---------------------------------------------------------------------------
__global__ __launch_bounds__(256) void gather_dot_kernel(
    const float* __restrict__ q_phi,
    const int*   __restrict__ k_indices,
    float* __restrict__ out,
    int nq)
{
    int t = blockIdx.x * blockDim.x + threadIdx.x;
    int i = t >> 3;
    if (i >= nq) return;
    int h = t & 7;

    int k = __ldg(k_indices + i);  // broadcast across the 8-thread group

    const float4* qp = reinterpret_cast<const float4*>(
        q_phi + (size_t)i * FEAT + h * MH_DIM);
    float4 q0 = __ldg(qp);
    float4 q1 = __ldg(qp + 1);

    const float4* pp = reinterpret_cast<const float4*>(
        g_pk + (size_t)k * REC + h * MH_DIM);
    float4 p0 = __ldg(pp);
    float4 p1 = __ldg(pp + 1);

    const float4* pn = reinterpret_cast<const float4*>(
        g_pk + (size_t)k * REC + FEAT + h * MH_DIM);
    float4 n0 = __ldg(pn);
    float4 n1 = __ldg(pn + 1);

    float dp = q0.x * p0.x + q0.y * p0.y + q0.z * p0.z + q0.w * p0.w
             + q1.x * p1.x + q1.y * p1.y + q1.z * p1.z + q1.w * p1.w;
    float dn = q0.x * n0.x + q0.y * n0.y + q0.z * n0.z + q0.w * n0.w
             + q1.x * n1.x + q1.y * n1.y + q1.z * n1.z + q1.w * n1.w;

    out[(size_t)i * H_DIM + h] = dp;
    out[(size_t)nq * H_DIM + (size_t)i * H_DIM + h] = dn;
}

extern "C" void kernel_launch(void* const* d_in, const int* in_sizes, int n_in,
                              void* d_out, int out_size)
{
    const float* q_phi   = (const float*)d_in[0];
    const float* phi_pos = (const float*)d_in[1];
    const float* phi_neg = (const float*)d_in[2];
    const float* deg_pos = (const float*)d_in[3];
    const float* deg_neg = (const float*)d_in[4];
    const int*   k_idx   = (const int*)d_in[5];

    int nq      = in_sizes[5];                    // k_indices has N_Q elements
    int n_nodes = in_sizes[3] / H_DIM;            // deg_pos is [N][H]
    if (n_nodes > MAX_NODES) n_nodes = MAX_NODES; // scratch capacity guard

    int tblocks = (n_nodes + 31) / 32;
    transpose_fold_kernel<<<tblocks, 256>>>(phi_pos, phi_neg, deg_pos, deg_neg,
                                            n_nodes);

    int total   = nq * H_DIM;
    int gblocks = (total + 255) / 256;
    gather_dot_kernel<<<gblocks, 256>>>(q_phi, k_idx, (float*)d_out, nq);
}

// round 3
// speedup vs baseline: 1.2110x; 1.2110x over previous
#include <cuda_runtime.h>
#include <cuda_fp16.h>
#include <cstdint>

// Problem constants (fixed-shape problem: H=8, MH=8, N_NODES=500000)
#define H_DIM 8
#define MH_DIM 8
#define FEAT 64              // H*MH per sign
#define REC 128              // 2 signs * FEAT values per node record
#define MAX_NODES 500000

// Node-major scratch in fp16: [node][sign][h][mh], 256B per node,
// deg-normalization folded in. Declared as uint4 to guarantee 16B alignment
// for the vectorized gather loads.
__device__ uint4 g_pk_raw[(size_t)MAX_NODES * REC / 8];

// ---------------------------------------------------------------------------
// Kernel 1: transpose [s][h][mh][N] (feature-major) -> [N][s][h][mh] fp16,
// multiplying by 1/max(deg,1) on the fly.
// Block: 256 threads handles a tile of 32 nodes x 128 features.
// ---------------------------------------------------------------------------
__global__ __launch_bounds__(256) void transpose_fold_kernel(
    const float* __restrict__ phi_pos,
    const float* __restrict__ phi_neg,
    const float* __restrict__ deg_pos,
    const float* __restrict__ deg_neg,
    int n_nodes)
{
    __shared__ float tile[32][REC + 1];  // [node][feat], +1 pad (odd stride: scalar reads only)
    __shared__ float inv[2][32][H_DIM];  // 1/max(deg,1) per (sign, node, head)

    const int k0 = blockIdx.x * 32;
    const int t  = threadIdx.x;

    // Load deg tiles (contiguous: deg_* is [N][H]) and invert with clamp.
    #pragma unroll
    for (int it = 0; it < 2; ++it) {
        int idx  = t + it * 256;          // 0..511 : s*256 + node*8 + h
        int s    = idx >> 8;
        int node = (idx >> 3) & 31;
        int h    = idx & 7;
        int k    = k0 + node;
        float d  = 1.0f;
        if (k < n_nodes) {
            const float* dp = s ? deg_neg : deg_pos;
            d = dp[(size_t)k * H_DIM + h];
        }
        inv[s][node][h] = 1.0f / fmaxf(d, 1.0f);
    }

    // Coalesced loads along the node (k) axis: 128 feature-rows x 32 nodes.
    // Lanes hold consecutive kk for fixed feature row r -> smem stride 129 -> no conflicts.
    #pragma unroll
    for (int it = 0; it < 16; ++it) {
        int l  = t + it * 256;
        int r  = l >> 5;        // feature row 0..127
        int kk = l & 31;        // node within tile
        int k  = k0 + kk;
        int s  = r >> 6;
        int f  = r & 63;        // h*8+mh
        float v = 0.0f;
        if (k < n_nodes) {
            const float* src = s ? phi_neg : phi_pos;
            v = __ldg(src + (size_t)f * n_nodes + k);
        }
        tile[kk][r] = v;
    }
    __syncthreads();

    // Convert+scale+store as half2: 32 nodes * 64 half2 = 2048 elements.
    // Lanes hold consecutive fpair for fixed node -> coalesced 4B stores.
    __half2* gp = reinterpret_cast<__half2*>(g_pk_raw);
    #pragma unroll
    for (int it = 0; it < 8; ++it) {
        int p     = t + it * 256;
        int node  = p >> 6;
        int fpair = p & 63;
        int k     = k0 + node;
        if (k < n_nodes) {
            int f0 = fpair * 2;              // even; f0,f0+1 share sign & head
            int s  = f0 >> 6;
            int h  = (f0 >> 3) & 7;
            float sc = inv[s][node][h];
            float v0 = tile[node][f0];
            float v1 = tile[node][f0 + 1];
            gp[(size_t)k * (REC / 2) + fpair] = __floats2half2_rn(v0 * sc, v1 * sc);
        }
    }
}

// ---------------------------------------------------------------------------
// Kernel 2: gather + dot. 8 threads per query; thread j handles head j for
// both signs. Gathers are 16B uint4 loads from a 256B-contiguous fp16 record.
// out layout: [pos: nq*8][neg: nq*8]
// ---------------------------------------------------------------------------
__global__ __launch_bounds__(256) void gather_dot_kernel(
    const float* __restrict__ q_phi,
    const int*   __restrict__ k_indices,
    float* __restrict__ out,
    int nq)
{
    int t = blockIdx.x * blockDim.x + threadIdx.x;
    int i = t >> 3;
    if (i >= nq) return;
    int h = t & 7;

    int k = __ldg(k_indices + i);  // broadcast across the 8-thread group

    const float4* qp = reinterpret_cast<const float4*>(
        q_phi + (size_t)i * FEAT + h * MH_DIM);
    float4 q0 = __ldg(qp);
    float4 q1 = __ldg(qp + 1);

    // Record = 16 uint4 (256B). pos: chunks [0..7], neg: chunks [8..15].
    // Head h owns chunk h (pos) and chunk 8+h (neg) — each 8 halves = 16B.
    const uint4* rec = g_pk_raw + (size_t)k * (REC / 8);
    uint4 pr = __ldg(rec + h);
    uint4 nr = __ldg(rec + 8 + h);

    const __half2* ph = reinterpret_cast<const __half2*>(&pr);
    const __half2* nh = reinterpret_cast<const __half2*>(&nr);

    float2 p0 = __half22float2(ph[0]);
    float2 p1 = __half22float2(ph[1]);
    float2 p2 = __half22float2(ph[2]);
    float2 p3 = __half22float2(ph[3]);
    float2 n0 = __half22float2(nh[0]);
    float2 n1 = __half22float2(nh[1]);
    float2 n2 = __half22float2(nh[2]);
    float2 n3 = __half22float2(nh[3]);

    float dp = q0.x * p0.x + q0.y * p0.y + q0.z * p1.x + q0.w * p1.y
             + q1.x * p2.x + q1.y * p2.y + q1.z * p3.x + q1.w * p3.y;
    float dn = q0.x * n0.x + q0.y * n0.y + q0.z * n1.x + q0.w * n1.y
             + q1.x * n2.x + q1.y * n2.y + q1.z * n3.x + q1.w * n3.y;

    out[(size_t)i * H_DIM + h] = dp;
    out[(size_t)nq * H_DIM + (size_t)i * H_DIM + h] = dn;
}

extern "C" void kernel_launch(void* const* d_in, const int* in_sizes, int n_in,
                              void* d_out, int out_size)
{
    const float* q_phi   = (const float*)d_in[0];
    const float* phi_pos = (const float*)d_in[1];
    const float* phi_neg = (const float*)d_in[2];
    const float* deg_pos = (const float*)d_in[3];
    const float* deg_neg = (const float*)d_in[4];
    const int*   k_idx   = (const int*)d_in[5];

    int nq      = in_sizes[5];                    // k_indices has N_Q elements
    int n_nodes = in_sizes[3] / H_DIM;            // deg_pos is [N][H]
    if (n_nodes > MAX_NODES) n_nodes = MAX_NODES; // scratch capacity guard

    int tblocks = (n_nodes + 31) / 32;
    transpose_fold_kernel<<<tblocks, 256>>>(phi_pos, phi_neg, deg_pos, deg_neg,
                                            n_nodes);

    int total   = nq * H_DIM;
    int gblocks = (total + 255) / 256;
    gather_dot_kernel<<<gblocks, 256>>>(q_phi, k_idx, (float*)d_out, nq);
}